// round 1
// baseline (speedup 1.0000x reference)
#include <cuda_runtime.h>
#include <math.h>
#include <stdint.h>

// Problem constants
#define BB  2
#define LL  4096
#define DD  2048
#define HH  16
#define KK  128
#define VV  128
#define MROWS (BB*LL)          // 8192
#define QSCALE 0.08838834764831845f   // 128^-0.5
#define LNEPS 1e-5f

// -------------------- scratch (device globals; no allocations) --------------------
__device__ float g_q [(size_t)MROWS * DD];   // also reused as LN output buffer
__device__ float g_k [(size_t)MROWS * DD];
__device__ float g_v [(size_t)MROWS * DD];
__device__ float g_eg[(size_t)MROWS * DD];   // sigmoid(x@Wg^T) = exp(log_sigmoid) decay
__device__ float g_y [(size_t)MROWS * DD];

__device__ __forceinline__ float* pick_buf(int sel, float* ext) {
    switch (sel) {
        case 1: return g_q;
        case 2: return g_k;
        case 3: return g_v;
        case 4: return g_eg;
        case 5: return g_y;
        default: return ext;
    }
}

// -------------------- GEMM: C[m,n] = act( sum_d A[m,d] * B[n,d] ) --------------------
// A: [M, Kd] row-major, B: [N, Kd] row-major (i.e. C = A @ B^T)
// MODE: 0 = identity, 1 = * QSCALE, 2 = sigmoid
template <int MODE>
__global__ __launch_bounds__(256)
void gemm_abt(const float* __restrict__ Aext, const float* __restrict__ Bmat,
              float* __restrict__ Cext, int Asel, int Csel,
              int M, int N, int Kd)
{
    __shared__ float As[8][132];
    __shared__ float Bs[8][132];

    const float* A = Asel ? (const float*)pick_buf(Asel, nullptr) : Aext;
    float*       C = Csel ? pick_buf(Csel, nullptr) : Cext;

    const int tid  = threadIdx.x;
    const int bm   = blockIdx.y * 128;
    const int bn   = blockIdx.x * 128;
    const int lrow = tid >> 1;          // 0..127
    const int lkg  = (tid & 1) << 2;    // 0 or 4
    const int tm   = (tid >> 4) << 3;   // 0..120 step 8
    const int tn   = (tid & 15) << 3;   // 0..120 step 8

    const float* Aptr = A    + (size_t)(bm + lrow) * Kd + lkg;
    const float* Bptr = Bmat + (size_t)(bn + lrow) * Kd + lkg;

    float acc[8][8];
    #pragma unroll
    for (int i = 0; i < 8; i++)
        #pragma unroll
        for (int j = 0; j < 8; j++) acc[i][j] = 0.f;

    for (int kt = 0; kt < Kd; kt += 8) {
        const float4 av = *(const float4*)(Aptr + kt);
        const float4 bv = *(const float4*)(Bptr + kt);
        __syncthreads();   // previous compute done before overwriting smem
        As[lkg + 0][lrow] = av.x;
        As[lkg + 1][lrow] = av.y;
        As[lkg + 2][lrow] = av.z;
        As[lkg + 3][lrow] = av.w;
        Bs[lkg + 0][lrow] = bv.x;
        Bs[lkg + 1][lrow] = bv.y;
        Bs[lkg + 2][lrow] = bv.z;
        Bs[lkg + 3][lrow] = bv.w;
        __syncthreads();

        #pragma unroll
        for (int kk = 0; kk < 8; kk++) {
            float ar[8], br[8];
            const float4 a0 = *(const float4*)&As[kk][tm];
            const float4 a1 = *(const float4*)&As[kk][tm + 4];
            const float4 b0 = *(const float4*)&Bs[kk][tn];
            const float4 b1 = *(const float4*)&Bs[kk][tn + 4];
            ar[0]=a0.x; ar[1]=a0.y; ar[2]=a0.z; ar[3]=a0.w;
            ar[4]=a1.x; ar[5]=a1.y; ar[6]=a1.z; ar[7]=a1.w;
            br[0]=b0.x; br[1]=b0.y; br[2]=b0.z; br[3]=b0.w;
            br[4]=b1.x; br[5]=b1.y; br[6]=b1.z; br[7]=b1.w;
            #pragma unroll
            for (int i = 0; i < 8; i++)
                #pragma unroll
                for (int j = 0; j < 8; j++)
                    acc[i][j] = fmaf(ar[i], br[j], acc[i][j]);
        }
    }

    #pragma unroll
    for (int i = 0; i < 8; i++) {
        float* Crow = C + (size_t)(bm + tm + i) * N + bn + tn;
        float o[8];
        #pragma unroll
        for (int j = 0; j < 8; j++) {
            float vv = acc[i][j];
            if (MODE == 1) vv *= QSCALE;
            if (MODE == 2) vv = 1.0f / (1.0f + __expf(-vv));
            o[j] = vv;
        }
        *(float4*)(Crow)     = make_float4(o[0], o[1], o[2], o[3]);
        *(float4*)(Crow + 4) = make_float4(o[4], o[5], o[6], o[7]);
    }
}

// -------------------- GLA recurrence --------------------
// grid: (4 v-chunks, H, B); block: 512 threads = 16 kq-groups (8 k each) x 32 v
// S[k,v] in registers; y_t[v] = sum_k q_t[k] * S_t[k,v] reduced via shfl over kq.
__global__ __launch_bounds__(512)
void gla_rec(float* __restrict__ out_state /* d_out + B*L*D */)
{
    const int tid  = threadIdx.x;
    const int kq   = tid & 15;         // 16 groups of 8 k
    const int vi   = tid >> 4;         // 0..31
    const int vabs = blockIdx.x * 32 + vi;
    const int h    = blockIdx.y;
    const int b    = blockIdx.z;

    const size_t base = ((size_t)b * LL) * DD + (size_t)h * KK;
    const float* qp = g_q  + base + kq * 8;
    const float* kp = g_k  + base + kq * 8;
    const float* gp = g_eg + base + kq * 8;
    const float* vp = g_v  + base + vabs;
    float*       yp = g_y  + base + vabs;

    float S[8] = {0.f,0.f,0.f,0.f,0.f,0.f,0.f,0.f};

    // prefetch t = 0
    float4 qa0 = *(const float4*)(qp);
    float4 qa1 = *(const float4*)(qp + 4);
    float4 ka0 = *(const float4*)(kp);
    float4 ka1 = *(const float4*)(kp + 4);
    float4 ga0 = *(const float4*)(gp);
    float4 ga1 = *(const float4*)(gp + 4);
    float  va  = *vp;

    for (int t = 0; t < LL; ++t) {
        const int tn = (t + 1 < LL) ? (t + 1) : t;
        const size_t noff = (size_t)tn * DD;
        const float4 qb0 = *(const float4*)(qp + noff);
        const float4 qb1 = *(const float4*)(qp + noff + 4);
        const float4 kb0 = *(const float4*)(kp + noff);
        const float4 kb1 = *(const float4*)(kp + noff + 4);
        const float4 gb0 = *(const float4*)(gp + noff);
        const float4 gb1 = *(const float4*)(gp + noff + 4);
        const float  vb  = vp[noff];

        float acc = 0.f;
        S[0] = fmaf(S[0], ga0.x, ka0.x * va); acc = fmaf(qa0.x, S[0], acc);
        S[1] = fmaf(S[1], ga0.y, ka0.y * va); acc = fmaf(qa0.y, S[1], acc);
        S[2] = fmaf(S[2], ga0.z, ka0.z * va); acc = fmaf(qa0.z, S[2], acc);
        S[3] = fmaf(S[3], ga0.w, ka0.w * va); acc = fmaf(qa0.w, S[3], acc);
        S[4] = fmaf(S[4], ga1.x, ka1.x * va); acc = fmaf(qa1.x, S[4], acc);
        S[5] = fmaf(S[5], ga1.y, ka1.y * va); acc = fmaf(qa1.y, S[5], acc);
        S[6] = fmaf(S[6], ga1.z, ka1.z * va); acc = fmaf(qa1.z, S[6], acc);
        S[7] = fmaf(S[7], ga1.w, ka1.w * va); acc = fmaf(qa1.w, S[7], acc);

        acc += __shfl_xor_sync(0xffffffffu, acc, 1);
        acc += __shfl_xor_sync(0xffffffffu, acc, 2);
        acc += __shfl_xor_sync(0xffffffffu, acc, 4);
        acc += __shfl_xor_sync(0xffffffffu, acc, 8);
        if (kq == 0) yp[(size_t)t * DD] = acc;

        qa0 = qb0; qa1 = qb1; ka0 = kb0; ka1 = kb1; ga0 = gb0; ga1 = gb1; va = vb;
    }

    // final state: [B, H, K, V]
    const size_t fsbase = (((size_t)(b * HH + h)) * KK + kq * 8) * VV + vabs;
    #pragma unroll
    for (int i = 0; i < 8; i++)
        out_state[fsbase + (size_t)i * VV] = S[i];
}

// -------------------- LayerNorm over last dim (D=2048) --------------------
// 1 CTA per row, 256 threads x 8 cols. Writes into g_q (reused as LN buffer).
__global__ __launch_bounds__(256)
void ln_kernel(const float* __restrict__ gamma, const float* __restrict__ beta)
{
    const int row = blockIdx.x;
    const float* yr = g_y + (size_t)row * DD;
    float*       orow = g_q + (size_t)row * DD;
    const int c0 = threadIdx.x * 8;

    const float4 v0 = *(const float4*)(yr + c0);
    const float4 v1 = *(const float4*)(yr + c0 + 4);
    float vals[8] = {v0.x, v0.y, v0.z, v0.w, v1.x, v1.y, v1.z, v1.w};

    float s = 0.f, s2 = 0.f;
    #pragma unroll
    for (int i = 0; i < 8; i++) { s += vals[i]; s2 = fmaf(vals[i], vals[i], s2); }

    #pragma unroll
    for (int m = 16; m >= 1; m >>= 1) {
        s  += __shfl_xor_sync(0xffffffffu, s,  m);
        s2 += __shfl_xor_sync(0xffffffffu, s2, m);
    }
    __shared__ float ws[8], ws2[8];
    const int warp = threadIdx.x >> 5;
    if ((threadIdx.x & 31) == 0) { ws[warp] = s; ws2[warp] = s2; }
    __syncthreads();
    float ts = 0.f, ts2 = 0.f;
    #pragma unroll
    for (int i = 0; i < 8; i++) { ts += ws[i]; ts2 += ws2[i]; }

    const float mu  = ts * (1.0f / DD);
    const float var = ts2 * (1.0f / DD) - mu * mu;
    const float r   = rsqrtf(var + LNEPS);

    const float4 ga0 = *(const float4*)(gamma + c0);
    const float4 ga1 = *(const float4*)(gamma + c0 + 4);
    const float4 be0 = *(const float4*)(beta + c0);
    const float4 be1 = *(const float4*)(beta + c0 + 4);
    float gm[8] = {ga0.x, ga0.y, ga0.z, ga0.w, ga1.x, ga1.y, ga1.z, ga1.w};
    float bt[8] = {be0.x, be0.y, be0.z, be0.w, be1.x, be1.y, be1.z, be1.w};

    float o[8];
    #pragma unroll
    for (int i = 0; i < 8; i++) o[i] = fmaf((vals[i] - mu) * r, gm[i], bt[i]);
    *(float4*)(orow + c0)     = make_float4(o[0], o[1], o[2], o[3]);
    *(float4*)(orow + c0 + 4) = make_float4(o[4], o[5], o[6], o[7]);
}

// -------------------- launch --------------------
extern "C" void kernel_launch(void* const* d_in, const int* in_sizes, int n_in,
                              void* d_out, int out_size)
{
    const float* x     = (const float*)d_in[0];
    const float* Wq    = (const float*)d_in[1];
    const float* Wk    = (const float*)d_in[2];
    const float* Wv    = (const float*)d_in[3];
    const float* Wg    = (const float*)d_in[4];
    const float* Wo    = (const float*)d_in[5];
    const float* gamma = (const float*)d_in[6];
    const float* beta  = (const float*)d_in[7];
    float* out = (float*)d_out;

    dim3 gblk(256);
    dim3 ggrid(DD / 128, MROWS / 128);   // (16, 64)

    // projections: q (scaled), k, v, eg = sigmoid(x Wg^T)
    gemm_abt<1><<<ggrid, gblk>>>(x, Wq, nullptr, 0, 1, MROWS, DD, DD);
    gemm_abt<0><<<ggrid, gblk>>>(x, Wk, nullptr, 0, 2, MROWS, DD, DD);
    gemm_abt<0><<<ggrid, gblk>>>(x, Wv, nullptr, 0, 3, MROWS, DD, DD);
    gemm_abt<2><<<ggrid, gblk>>>(x, Wg, nullptr, 0, 4, MROWS, DD, DD);

    // recurrence: writes y (g_y) and final_state (tail of d_out)
    gla_rec<<<dim3(4, HH, BB), 512>>>(out + (size_t)MROWS * DD);

    // layernorm into g_q (reuse), then output projection into d_out
    ln_kernel<<<MROWS, 256>>>(gamma, beta);
    gemm_abt<0><<<ggrid, gblk>>>(nullptr, Wo, out, 1, 0, MROWS, DD, DD);
}

// round 2
// speedup vs baseline: 2.1643x; 2.1643x over previous
#include <cuda_runtime.h>
#include <math.h>
#include <stdint.h>

// Problem constants
#define BB  2
#define LL  4096
#define DD  2048
#define HH  16
#define KK  128
#define VV  128
#define MROWS (BB*LL)          // 8192
#define QSCALE 0.08838834764831845f   // 128^-0.5
#define LNEPS 1e-5f

// GEMM tiling
#define BM 128
#define BN 128
#define BK 32
#define PADK 36   // BK + 4  -> conflict-free smem (stride mod 32 == 4)

// -------------------- scratch (device globals; no allocations) --------------------
__device__ float g_q [(size_t)MROWS * DD];   // also reused as LN output buffer
__device__ float g_k [(size_t)MROWS * DD];
__device__ float g_v [(size_t)MROWS * DD];
__device__ float g_eg[(size_t)MROWS * DD];   // sigmoid(x@Wg^T) decay
__device__ float g_y [(size_t)MROWS * DD];
__device__ float g_xt[(size_t)MROWS * DD];   // tf32-rounded x
__device__ float g_w [5][(size_t)DD * DD];   // tf32-rounded weights

__device__ __forceinline__ float* pick_buf(int sel) {
    switch (sel) {
        case 1: return g_q;
        case 2: return g_k;
        case 3: return g_v;
        case 4: return g_eg;
        case 5: return g_y;
        case 6: return g_xt;
        default: return g_w[sel - 7];   // 7..11
    }
}

// -------------------- tf32 rounding pre-pass --------------------
__device__ __forceinline__ float tf32_rna(float f) {
    uint32_t u;
    asm("cvt.rna.tf32.f32 %0, %1;" : "=r"(u) : "f"(f));
    return __uint_as_float(u);
}

__global__ __launch_bounds__(256)
void tf32_round_kernel(const float* __restrict__ in, int outsel, int n)
{
    float* out = pick_buf(outsel);
    int i = (blockIdx.x * 256 + threadIdx.x) * 4;
    if (i < n) {
        float4 v = *(const float4*)(in + i);
        v.x = tf32_rna(v.x); v.y = tf32_rna(v.y);
        v.z = tf32_rna(v.z); v.w = tf32_rna(v.w);
        *(float4*)(out + i) = v;
    }
}

// -------------------- tf32 tensor-core GEMM: C = act(A @ B^T) --------------------
// A: [M, Kd] row-major (scratch sel), B: [N, Kd] row-major (scratch sel).
// MODE: 0 = identity, 1 = * QSCALE, 2 = sigmoid
__device__ __forceinline__ void mma_tf32(float* c, const uint32_t* a, const uint32_t* b)
{
    asm volatile(
        "mma.sync.aligned.m16n8k8.row.col.f32.tf32.tf32.f32 "
        "{%0,%1,%2,%3},{%4,%5,%6,%7},{%8,%9},{%0,%1,%2,%3};\n"
        : "+f"(c[0]), "+f"(c[1]), "+f"(c[2]), "+f"(c[3])
        : "r"(a[0]), "r"(a[1]), "r"(a[2]), "r"(a[3]), "r"(b[0]), "r"(b[1]));
}

__device__ __forceinline__ void cp16(uint32_t sa, const float* g)
{
    asm volatile("cp.async.cg.shared.global [%0], [%1], 16;\n" :: "r"(sa), "l"(g));
}

template <int MODE>
__global__ __launch_bounds__(256)
void gemm_tf32(int Asel, int Bsel, float* __restrict__ Cext, int Csel,
               int M, int N, int Kd)
{
    extern __shared__ float sm[];
    // layout: As[2][BM][PADK] then Bs[2][BN][PADK]
    float* Asm = sm;
    float* Bsm = sm + 2 * BM * PADK;

    const float* A = (const float*)pick_buf(Asel);
    const float* B = (const float*)pick_buf(Bsel);
    float*       C = Csel ? pick_buf(Csel) : Cext;

    const int tid  = threadIdx.x;
    const int bm   = blockIdx.y * BM;
    const int bn   = blockIdx.x * BN;
    const int warp = tid >> 5, lane = tid & 31;
    const int wm   = (warp >> 2) * 64;   // 2 warp rows
    const int wn   = (warp & 3) * 32;    // 4 warp cols
    const int grp  = lane >> 2, t4 = lane & 3;

    const int lrow = tid >> 3;        // 0..31 (then +32,+64,+96)
    const int lk   = (tid & 7) * 4;   // 0..28 step 4

    uint32_t smb = (uint32_t)__cvta_generic_to_shared(sm);
    uint32_t AsB = smb;
    uint32_t BsB = smb + 2 * BM * PADK * 4;

    float acc[4][4][4];
    #pragma unroll
    for (int i = 0; i < 4; i++)
        #pragma unroll
        for (int j = 0; j < 4; j++)
            #pragma unroll
            for (int e = 0; e < 4; e++) acc[i][j][e] = 0.f;

    const int nk = Kd / BK;

    auto issue_chunk = [&](int buf, int kt) {
        #pragma unroll
        for (int i = 0; i < 4; i++) {
            int row = lrow + 32 * i;
            cp16(AsB + (uint32_t)((buf * BM + row) * PADK + lk) * 4,
                 A + (size_t)(bm + row) * Kd + kt + lk);
            cp16(BsB + (uint32_t)((buf * BN + row) * PADK + lk) * 4,
                 B + (size_t)(bn + row) * Kd + kt + lk);
        }
        asm volatile("cp.async.commit_group;\n");
    };

    issue_chunk(0, 0);

    for (int kt = 0; kt < nk; kt++) {
        if (kt + 1 < nk) issue_chunk((kt + 1) & 1, (kt + 1) * BK);
        else             asm volatile("cp.async.commit_group;\n");
        asm volatile("cp.async.wait_group 1;\n");
        __syncthreads();

        const float* Ab = Asm + (kt & 1) * BM * PADK;
        const float* Bb = Bsm + (kt & 1) * BN * PADK;

        #pragma unroll
        for (int k8 = 0; k8 < BK; k8 += 8) {
            uint32_t a[4][4], b[4][2];
            #pragma unroll
            for (int i = 0; i < 4; i++) {
                const float* ap = Ab + (wm + i * 16 + grp) * PADK + k8 + t4;
                a[i][0] = __float_as_uint(ap[0]);
                a[i][1] = __float_as_uint(ap[8 * PADK]);
                a[i][2] = __float_as_uint(ap[4]);
                a[i][3] = __float_as_uint(ap[8 * PADK + 4]);
            }
            #pragma unroll
            for (int j = 0; j < 4; j++) {
                const float* bp = Bb + (wn + j * 8 + grp) * PADK + k8 + t4;
                b[j][0] = __float_as_uint(bp[0]);
                b[j][1] = __float_as_uint(bp[4]);
            }
            #pragma unroll
            for (int i = 0; i < 4; i++)
                #pragma unroll
                for (int j = 0; j < 4; j++)
                    mma_tf32(acc[i][j], a[i], b[j]);
        }
        __syncthreads();
    }

    // epilogue
    #pragma unroll
    for (int i = 0; i < 4; i++) {
        const int r0 = bm + wm + i * 16 + grp;
        #pragma unroll
        for (int j = 0; j < 4; j++) {
            const int c0 = bn + wn + j * 8 + t4 * 2;
            float o[4];
            #pragma unroll
            for (int e = 0; e < 4; e++) {
                float vv = acc[i][j][e];
                if (MODE == 1) vv *= QSCALE;
                if (MODE == 2) vv = 1.0f / (1.0f + __expf(-vv));
                o[e] = vv;
            }
            *(float2*)&C[(size_t)r0 * N + c0]       = make_float2(o[0], o[1]);
            *(float2*)&C[(size_t)(r0 + 8) * N + c0] = make_float2(o[2], o[3]);
        }
    }
}

// -------------------- GLA recurrence --------------------
__global__ __launch_bounds__(512)
void gla_rec(float* __restrict__ out_state)
{
    const int tid  = threadIdx.x;
    const int kq   = tid & 15;
    const int vi   = tid >> 4;
    const int vabs = blockIdx.x * 32 + vi;
    const int h    = blockIdx.y;
    const int b    = blockIdx.z;

    const size_t base = ((size_t)b * LL) * DD + (size_t)h * KK;
    const float* qp = g_q  + base + kq * 8;
    const float* kp = g_k  + base + kq * 8;
    const float* gp = g_eg + base + kq * 8;
    const float* vp = g_v  + base + vabs;
    float*       yp = g_y  + base + vabs;

    float S[8] = {0.f,0.f,0.f,0.f,0.f,0.f,0.f,0.f};

    float4 qa0 = *(const float4*)(qp);
    float4 qa1 = *(const float4*)(qp + 4);
    float4 ka0 = *(const float4*)(kp);
    float4 ka1 = *(const float4*)(kp + 4);
    float4 ga0 = *(const float4*)(gp);
    float4 ga1 = *(const float4*)(gp + 4);
    float  va  = *vp;

    for (int t = 0; t < LL; ++t) {
        const int tn = (t + 1 < LL) ? (t + 1) : t;
        const size_t noff = (size_t)tn * DD;
        const float4 qb0 = *(const float4*)(qp + noff);
        const float4 qb1 = *(const float4*)(qp + noff + 4);
        const float4 kb0 = *(const float4*)(kp + noff);
        const float4 kb1 = *(const float4*)(kp + noff + 4);
        const float4 gb0 = *(const float4*)(gp + noff);
        const float4 gb1 = *(const float4*)(gp + noff + 4);
        const float  vb  = vp[noff];

        float acc = 0.f;
        S[0] = fmaf(S[0], ga0.x, ka0.x * va); acc = fmaf(qa0.x, S[0], acc);
        S[1] = fmaf(S[1], ga0.y, ka0.y * va); acc = fmaf(qa0.y, S[1], acc);
        S[2] = fmaf(S[2], ga0.z, ka0.z * va); acc = fmaf(qa0.z, S[2], acc);
        S[3] = fmaf(S[3], ga0.w, ka0.w * va); acc = fmaf(qa0.w, S[3], acc);
        S[4] = fmaf(S[4], ga1.x, ka1.x * va); acc = fmaf(qa1.x, S[4], acc);
        S[5] = fmaf(S[5], ga1.y, ka1.y * va); acc = fmaf(qa1.y, S[5], acc);
        S[6] = fmaf(S[6], ga1.z, ka1.z * va); acc = fmaf(qa1.z, S[6], acc);
        S[7] = fmaf(S[7], ga1.w, ka1.w * va); acc = fmaf(qa1.w, S[7], acc);

        acc += __shfl_xor_sync(0xffffffffu, acc, 1);
        acc += __shfl_xor_sync(0xffffffffu, acc, 2);
        acc += __shfl_xor_sync(0xffffffffu, acc, 4);
        acc += __shfl_xor_sync(0xffffffffu, acc, 8);
        if (kq == 0) yp[(size_t)t * DD] = acc;

        qa0 = qb0; qa1 = qb1; ka0 = kb0; ka1 = kb1; ga0 = gb0; ga1 = gb1; va = vb;
    }

    const size_t fsbase = (((size_t)(b * HH + h)) * KK + kq * 8) * VV + vabs;
    #pragma unroll
    for (int i = 0; i < 8; i++)
        out_state[fsbase + (size_t)i * VV] = S[i];
}

// -------------------- LayerNorm (writes tf32-rounded output for Wo GEMM) -----
__global__ __launch_bounds__(256)
void ln_kernel(const float* __restrict__ gamma, const float* __restrict__ beta)
{
    const int row = blockIdx.x;
    const float* yr   = g_y + (size_t)row * DD;
    float*       orow = g_q + (size_t)row * DD;
    const int c0 = threadIdx.x * 8;

    const float4 v0 = *(const float4*)(yr + c0);
    const float4 v1 = *(const float4*)(yr + c0 + 4);
    float vals[8] = {v0.x, v0.y, v0.z, v0.w, v1.x, v1.y, v1.z, v1.w};

    float s = 0.f, s2 = 0.f;
    #pragma unroll
    for (int i = 0; i < 8; i++) { s += vals[i]; s2 = fmaf(vals[i], vals[i], s2); }

    #pragma unroll
    for (int m = 16; m >= 1; m >>= 1) {
        s  += __shfl_xor_sync(0xffffffffu, s,  m);
        s2 += __shfl_xor_sync(0xffffffffu, s2, m);
    }
    __shared__ float ws[8], ws2[8];
    const int warp = threadIdx.x >> 5;
    if ((threadIdx.x & 31) == 0) { ws[warp] = s; ws2[warp] = s2; }
    __syncthreads();
    float ts = 0.f, ts2 = 0.f;
    #pragma unroll
    for (int i = 0; i < 8; i++) { ts += ws[i]; ts2 += ws2[i]; }

    const float mu  = ts * (1.0f / DD);
    const float var = ts2 * (1.0f / DD) - mu * mu;
    const float r   = rsqrtf(var + LNEPS);

    const float4 ga0 = *(const float4*)(gamma + c0);
    const float4 ga1 = *(const float4*)(gamma + c0 + 4);
    const float4 be0 = *(const float4*)(beta + c0);
    const float4 be1 = *(const float4*)(beta + c0 + 4);
    float gm[8] = {ga0.x, ga0.y, ga0.z, ga0.w, ga1.x, ga1.y, ga1.z, ga1.w};
    float bt[8] = {be0.x, be0.y, be0.z, be0.w, be1.x, be1.y, be1.z, be1.w};

    float o[8];
    #pragma unroll
    for (int i = 0; i < 8; i++)
        o[i] = tf32_rna(fmaf((vals[i] - mu) * r, gm[i], bt[i]));
    *(float4*)(orow + c0)     = make_float4(o[0], o[1], o[2], o[3]);
    *(float4*)(orow + c0 + 4) = make_float4(o[4], o[5], o[6], o[7]);
}

// -------------------- launch --------------------
extern "C" void kernel_launch(void* const* d_in, const int* in_sizes, int n_in,
                              void* d_out, int out_size)
{
    const float* x     = (const float*)d_in[0];
    const float* Wq    = (const float*)d_in[1];
    const float* Wk    = (const float*)d_in[2];
    const float* Wv    = (const float*)d_in[3];
    const float* Wg    = (const float*)d_in[4];
    const float* Wo    = (const float*)d_in[5];
    const float* gamma = (const float*)d_in[6];
    const float* beta  = (const float*)d_in[7];
    float* out = (float*)d_out;

    const int smem = 4 * BM * PADK * 4;   // 73728 bytes
    cudaFuncSetAttribute(gemm_tf32<0>, cudaFuncAttributeMaxDynamicSharedMemorySize, smem);
    cudaFuncSetAttribute(gemm_tf32<1>, cudaFuncAttributeMaxDynamicSharedMemorySize, smem);
    cudaFuncSetAttribute(gemm_tf32<2>, cudaFuncAttributeMaxDynamicSharedMemorySize, smem);

    // tf32 rounding pre-pass
    const int nx = MROWS * DD;            // 16M
    const int nw = DD * DD;               // 4M
    tf32_round_kernel<<<nx / (256 * 4), 256>>>(x,  6, nx);
    tf32_round_kernel<<<nw / (256 * 4), 256>>>(Wq, 7, nw);
    tf32_round_kernel<<<nw / (256 * 4), 256>>>(Wk, 8, nw);
    tf32_round_kernel<<<nw / (256 * 4), 256>>>(Wv, 9, nw);
    tf32_round_kernel<<<nw / (256 * 4), 256>>>(Wg, 10, nw);
    tf32_round_kernel<<<nw / (256 * 4), 256>>>(Wo, 11, nw);

    dim3 ggrid(DD / BN, MROWS / BM);   // (16, 64)

    // projections: q (scaled), k, v, eg = sigmoid(x Wg^T)
    gemm_tf32<1><<<ggrid, 256, smem>>>(6, 7,  nullptr, 1, MROWS, DD, DD);
    gemm_tf32<0><<<ggrid, 256, smem>>>(6, 8,  nullptr, 2, MROWS, DD, DD);
    gemm_tf32<0><<<ggrid, 256, smem>>>(6, 9,  nullptr, 3, MROWS, DD, DD);
    gemm_tf32<2><<<ggrid, 256, smem>>>(6, 10, nullptr, 4, MROWS, DD, DD);

    // recurrence: writes y (g_y) and final_state (tail of d_out)
    gla_rec<<<dim3(4, HH, BB), 512>>>(out + (size_t)MROWS * DD);

    // layernorm into g_q (tf32-rounded), then output projection into d_out
    ln_kernel<<<MROWS, 256>>>(gamma, beta);
    gemm_tf32<0><<<ggrid, 256, smem>>>(1, 11, out, 0, MROWS, DD, DD);
}